// round 11
// baseline (speedup 1.0000x reference)
#include <cuda_runtime.h>

typedef unsigned long long ull;

// Fixed problem shape: N=100000, IN=256, OUT=64, E=1600000 (guarded by in_sizes).
#define NMAX 100000
#define IN_DIM 256
#define OUT_DIM 64

__device__ __align__(16) float g_h[(size_t)NMAX * OUT_DIM];
__device__ float g_asrc[NMAX];
__device__ float g_adst[NMAX];
__device__ float g_emax[NMAX];
__device__ float g_denom[NMAX];

// ---------- packed f32x2 helpers (Blackwell) ----------
__device__ __forceinline__ ull packdup(float v) {
    ull r; asm("mov.b64 %0, {%1, %1};" : "=l"(r) : "f"(v)); return r;
}
__device__ __forceinline__ void fma2(ull& d, ull a, ull b) {
    asm("fma.rn.f32x2 %0, %1, %2, %0;" : "+l"(d) : "l"(a), "l"(b));
}
__device__ __forceinline__ void unpack2(ull v, float& a, float& b) {
    asm("mov.b64 {%0, %1}, %2;" : "=f"(a), "=f"(b) : "l"(v));
}

// vector reduction-add to global (sm_90+), 16B per op
__device__ __forceinline__ void red_add4(float* p, float a, float b, float c, float d) {
    asm volatile("red.global.add.v4.f32 [%0], {%1, %2, %3, %4};"
                 :: "l"(p), "f"(a), "f"(b), "f"(c), "f"(d) : "memory");
}

// float atomic max via int/uint ordering trick (init must be -inf)
__device__ __forceinline__ void atomicMaxF(float* addr, float val) {
    if (val >= 0.f) atomicMax((int*)addr, __float_as_int(val));
    else            atomicMin((unsigned int*)addr, __float_as_uint(val));
}

__device__ __forceinline__ float lrelu(float v) {
    return fmaxf(v, 0.f) + 0.2f * fminf(v, 0.f);
}

__device__ __forceinline__ int clampi(int v, int hi) {   // [0, hi)
    return min(max(v, 0), hi - 1);
}

// ---------- K0: init out=0, denom=0, emax=-inf ----------
__global__ void k_init(float* __restrict__ out, int n_out, int N) {
    int i = blockIdx.x * blockDim.x + threadIdx.x;
    if (i < n_out) out[i] = 0.f;
    if (i < N) { g_denom[i] = 0.f; g_emax[i] = __int_as_float(0xff800000); }
}

// ---------- K1: h = x @ W, a_src = h@att_src, a_dst = h@att_dst ----------
// 64x64 output tile per block, 256 threads (16x16), 4x4 register tile,
// inner product via packed fma.rn.f32x2 (2 cols per op).
#define TM 64
#define TK 32
__global__ __launch_bounds__(256)
void k_gemm(const float* __restrict__ x, const float* __restrict__ W,
            const float* __restrict__ att_s, const float* __restrict__ att_d, int N) {
    __shared__ float xs[TM][TK + 1];   // [m][k], stride 33: conflict-free scalar STS + broadcast LDS
    __shared__ float ws[TK][OUT_DIM];  // [k][n], natural row-major

    const int tid = threadIdx.x;
    const int tx = tid & 15;          // col group (4 cols)
    const int ty = tid >> 4;          // row group (4 rows)
    const int row0 = blockIdx.x * TM;

    ull acc[4][2];
#pragma unroll
    for (int i = 0; i < 4; i++) { acc[i][0] = 0ull; acc[i][1] = 0ull; }

    for (int kc = 0; kc < IN_DIM; kc += TK) {
        // load x tile: 64 rows x 32 k = 512 float4
#pragma unroll
        for (int it = 0; it < 2; ++it) {
            int idx = tid + it * 256;          // 0..511
            int m   = idx >> 3;                // row in tile
            int kq  = idx & 7;                 // float4 within k-chunk
            int gr  = row0 + m;
            float4 v = make_float4(0.f, 0.f, 0.f, 0.f);
            if (gr < N) v = *(const float4*)(x + (long long)gr * IN_DIM + kc + kq * 4);
            xs[m][kq * 4 + 0] = v.x; xs[m][kq * 4 + 1] = v.y;
            xs[m][kq * 4 + 2] = v.z; xs[m][kq * 4 + 3] = v.w;
        }
        // load W tile: 32 k x 64 n = 512 float4
#pragma unroll
        for (int it = 0; it < 2; ++it) {
            int idx = tid + it * 256;
            int k   = idx >> 4;
            int nq  = idx & 15;
            *(float4*)&ws[k][nq * 4] =
                *(const float4*)(W + (long long)(kc + k) * OUT_DIM + nq * 4);
        }
        __syncthreads();

#pragma unroll
        for (int k = 0; k < TK; ++k) {
            ulonglong2 bv = *(const ulonglong2*)&ws[k][tx * 4];  // (n0,n1),(n2,n3) packed
            float a0 = xs[ty * 4 + 0][k];
            float a1 = xs[ty * 4 + 1][k];
            float a2 = xs[ty * 4 + 2][k];
            float a3 = xs[ty * 4 + 3][k];
            ull A;
            A = packdup(a0); fma2(acc[0][0], A, bv.x); fma2(acc[0][1], A, bv.y);
            A = packdup(a1); fma2(acc[1][0], A, bv.x); fma2(acc[1][1], A, bv.y);
            A = packdup(a2); fma2(acc[2][0], A, bv.x); fma2(acc[2][1], A, bv.y);
            A = packdup(a3); fma2(acc[3][0], A, bv.x); fma2(acc[3][1], A, bv.y);
        }
        __syncthreads();
    }

    // unpack 4x4 tile
    float f[4][4];
#pragma unroll
    for (int i = 0; i < 4; i++) {
        unpack2(acc[i][0], f[i][0], f[i][1]);
        unpack2(acc[i][1], f[i][2], f[i][3]);
    }

    float as[4], ad[4];
#pragma unroll
    for (int j = 0; j < 4; j++) { as[j] = att_s[tx * 4 + j]; ad[j] = att_d[tx * 4 + j]; }

#pragma unroll
    for (int i = 0; i < 4; i++) {
        int gr = row0 + ty * 4 + i;
        if (gr < N)
            *(float4*)&g_h[(long long)gr * OUT_DIM + tx * 4] =
                make_float4(f[i][0], f[i][1], f[i][2], f[i][3]);
        float ps = f[i][0] * as[0] + f[i][1] * as[1] + f[i][2] * as[2] + f[i][3] * as[3];
        float pd = f[i][0] * ad[0] + f[i][1] * ad[1] + f[i][2] * ad[2] + f[i][3] * ad[3];
#pragma unroll
        for (int o = 8; o >= 1; o >>= 1) {
            ps += __shfl_xor_sync(0xffffffffu, ps, o);
            pd += __shfl_xor_sync(0xffffffffu, pd, o);
        }
        if (tx == 0 && gr < N) { g_asrc[gr] = ps; g_adst[gr] = pd; }
    }
}

// ---------- K2: segment max over destinations (edges + self loops) ----------
// edge_index is INT32 (JAX default x64-disabled downcasts int64 -> int32).
__global__ __launch_bounds__(256)
void k_edge_max(const int* __restrict__ ei, int E, int N) {
    long long idx = (long long)blockIdx.x * blockDim.x + threadIdx.x;
    long long ET = (long long)E + N;
    if (idx >= ET) return;
    int s, d;
    if (idx < E) { s = clampi(ei[idx], N); d = clampi(ei[E + idx], N); }
    else         { s = d = (int)(idx - E); }
    float v = lrelu(g_asrc[s] + g_adst[d]);
    atomicMaxF(&g_emax[d], v);
}

// ---------- K3: w = exp(e - emax[dst]); denom[dst] += w; out[dst] += w*h[src] ----------
// 16 threads per edge; each thread covers 4 output dims via red.v4.f32.
__global__ __launch_bounds__(256)
void k_edge_scatter(const int* __restrict__ ei, int E, int N,
                    float* __restrict__ out) {
    long long gid = (long long)blockIdx.x * blockDim.x + threadIdx.x;
    long long e = gid >> 4;
    int t = (int)(gid & 15);
    long long ET = (long long)E + N;
    if (e >= ET) return;
    int s, d;
    if (e < E) { s = clampi(ei[e], N); d = clampi(ei[E + e], N); }
    else       { s = d = (int)(e - E); }
    float v = lrelu(g_asrc[s] + g_adst[d]);
    float w = __expf(v - g_emax[d]);
    if (t == 0) atomicAdd(&g_denom[d], w);
    float4 hv = *(const float4*)&g_h[(long long)s * OUT_DIM + t * 4];
    red_add4(out + (long long)d * OUT_DIM + t * 4, w * hv.x, w * hv.y, w * hv.z, w * hv.w);
}

// ---------- K4: out = (acc/denom + bias), then row-wise L2 normalize ----------
__global__ __launch_bounds__(256)
void k_finalize(float* __restrict__ out, const float* __restrict__ bias, int N) {
    int gid = blockIdx.x * blockDim.x + threadIdx.x;
    int row = gid >> 5;
    int lane = gid & 31;
    if (row >= N) return;
    float inv = 1.f / g_denom[row];
    float o0 = out[(long long)row * OUT_DIM + lane]      * inv + bias[lane];
    float o1 = out[(long long)row * OUT_DIM + 32 + lane] * inv + bias[32 + lane];
    float ss = o0 * o0 + o1 * o1;
#pragma unroll
    for (int o = 16; o >= 1; o >>= 1) ss += __shfl_xor_sync(0xffffffffu, ss, o);
    float nrm = sqrtf(ss);
    float sc = 1.f / fmaxf(nrm, 1e-12f);
    out[(long long)row * OUT_DIM + lane]      = o0 * sc;
    out[(long long)row * OUT_DIM + 32 + lane] = o1 * sc;
}

static inline int grid1(long long work, int block) {
    long long g = (work + block - 1) / block;
    return (int)(g < 1 ? 1 : g);
}

extern "C" void kernel_launch(void* const* d_in, const int* in_sizes, int n_in,
                              void* d_out, int out_size) {
    const float* x     = (const float*)d_in[0];
    const int*   ei    = (const int*)d_in[1];     // int32! (JAX x64 disabled)
    const float* W     = (const float*)d_in[2];
    const float* att_s = (const float*)d_in[3];
    const float* att_d = (const float*)d_in[4];
    const float* bias  = (const float*)d_in[5];
    float* out = (float*)d_out;

    int       N  = in_sizes[0] / IN_DIM;
    int       E  = in_sizes[1] / 2;
    long long ET = (long long)E + N;

    // K0: init
    k_init<<<grid1((long long)N * OUT_DIM, 256), 256>>>(out, N * OUT_DIM, N);
    // K1: GEMM + attention scores
    k_gemm<<<grid1(N, TM), 256>>>(x, W, att_s, att_d, N);
    // K2: segment max
    k_edge_max<<<grid1(ET, 256), 256>>>(ei, E, N);
    // K3: exp + denom + weighted scatter
    k_edge_scatter<<<grid1(ET * 16, 256), 256>>>(ei, E, N, out);
    // K4: finalize (divide, bias, L2 normalize)
    k_finalize<<<grid1((long long)N * 32, 256), 256>>>(out, bias, N);
}

// round 14
// speedup vs baseline: 1.2457x; 1.2457x over previous
#include <cuda_runtime.h>

typedef unsigned long long ull;

// Fixed problem shape: N=100000, IN=256, OUT=64, E=1600000 (guarded by in_sizes).
#define NMAX 100000
#define EMAX 1600000
#define ETMAX (NMAX + EMAX)
#define IN_DIM 256
#define OUT_DIM 64
#define SCAN_B 512

__device__ __align__(16) float g_h[(size_t)NMAX * OUT_DIM];
__device__ float g_asrc[NMAX];
__device__ float g_adst[NMAX];
__device__ int   g_count[NMAX];      // in-degree (incl self loop)
__device__ int   g_rowstart[NMAX];   // exclusive prefix of count
__device__ int   g_cursor[NMAX];     // bucket-fill cursor
__device__ int   g_part[1024];       // scan partials
__device__ int   g_esrc[ETMAX];      // edge sources bucketed by dst

// ---------- packed f32x2 helpers (Blackwell) ----------
__device__ __forceinline__ ull packdup(float v) {
    ull r; asm("mov.b64 %0, {%1, %1};" : "=l"(r) : "f"(v)); return r;
}
__device__ __forceinline__ void fma2(ull& d, ull a, ull b) {
    asm("fma.rn.f32x2 %0, %1, %2, %0;" : "+l"(d) : "l"(a), "l"(b));
}
__device__ __forceinline__ void unpack2(ull v, float& a, float& b) {
    asm("mov.b64 {%0, %1}, %2;" : "=f"(a), "=f"(b) : "l"(v));
}

__device__ __forceinline__ float lrelu(float v) {
    return fmaxf(v, 0.f) + 0.2f * fminf(v, 0.f);
}
__device__ __forceinline__ int clampi(int v, int hi) { return min(max(v, 0), hi - 1); }

// ---------- K0: zero degree counters ----------
__global__ void k_init(int N) {
    int i = blockIdx.x * blockDim.x + threadIdx.x;
    if (i < N) g_count[i] = 0;
}

// ---------- K1: h = x @ W, a_src = h@att_src, a_dst = h@att_dst ----------
#define TM 64
#define TK 32
__global__ __launch_bounds__(256)
void k_gemm(const float* __restrict__ x, const float* __restrict__ W,
            const float* __restrict__ att_s, const float* __restrict__ att_d, int N) {
    __shared__ float xs[TM][TK + 1];
    __shared__ float ws[TK][OUT_DIM];

    const int tid = threadIdx.x;
    const int tx = tid & 15;
    const int ty = tid >> 4;
    const int row0 = blockIdx.x * TM;

    ull acc[4][2];
#pragma unroll
    for (int i = 0; i < 4; i++) { acc[i][0] = 0ull; acc[i][1] = 0ull; }

    for (int kc = 0; kc < IN_DIM; kc += TK) {
#pragma unroll
        for (int it = 0; it < 2; ++it) {
            int idx = tid + it * 256;
            int m   = idx >> 3;
            int kq  = idx & 7;
            int gr  = row0 + m;
            float4 v = make_float4(0.f, 0.f, 0.f, 0.f);
            if (gr < N) v = *(const float4*)(x + (long long)gr * IN_DIM + kc + kq * 4);
            xs[m][kq * 4 + 0] = v.x; xs[m][kq * 4 + 1] = v.y;
            xs[m][kq * 4 + 2] = v.z; xs[m][kq * 4 + 3] = v.w;
        }
#pragma unroll
        for (int it = 0; it < 2; ++it) {
            int idx = tid + it * 256;
            int k   = idx >> 4;
            int nq  = idx & 15;
            *(float4*)&ws[k][nq * 4] =
                *(const float4*)(W + (long long)(kc + k) * OUT_DIM + nq * 4);
        }
        __syncthreads();

#pragma unroll
        for (int k = 0; k < TK; ++k) {
            ulonglong2 bv = *(const ulonglong2*)&ws[k][tx * 4];
            float a0 = xs[ty * 4 + 0][k];
            float a1 = xs[ty * 4 + 1][k];
            float a2 = xs[ty * 4 + 2][k];
            float a3 = xs[ty * 4 + 3][k];
            ull A;
            A = packdup(a0); fma2(acc[0][0], A, bv.x); fma2(acc[0][1], A, bv.y);
            A = packdup(a1); fma2(acc[1][0], A, bv.x); fma2(acc[1][1], A, bv.y);
            A = packdup(a2); fma2(acc[2][0], A, bv.x); fma2(acc[2][1], A, bv.y);
            A = packdup(a3); fma2(acc[3][0], A, bv.x); fma2(acc[3][1], A, bv.y);
        }
        __syncthreads();
    }

    float f[4][4];
#pragma unroll
    for (int i = 0; i < 4; i++) {
        unpack2(acc[i][0], f[i][0], f[i][1]);
        unpack2(acc[i][1], f[i][2], f[i][3]);
    }

    float as[4], ad[4];
#pragma unroll
    for (int j = 0; j < 4; j++) { as[j] = att_s[tx * 4 + j]; ad[j] = att_d[tx * 4 + j]; }

#pragma unroll
    for (int i = 0; i < 4; i++) {
        int gr = row0 + ty * 4 + i;
        if (gr < N)
            *(float4*)&g_h[(long long)gr * OUT_DIM + tx * 4] =
                make_float4(f[i][0], f[i][1], f[i][2], f[i][3]);
        float ps = f[i][0] * as[0] + f[i][1] * as[1] + f[i][2] * as[2] + f[i][3] * as[3];
        float pd = f[i][0] * ad[0] + f[i][1] * ad[1] + f[i][2] * ad[2] + f[i][3] * ad[3];
#pragma unroll
        for (int o = 8; o >= 1; o >>= 1) {
            ps += __shfl_xor_sync(0xffffffffu, ps, o);
            pd += __shfl_xor_sync(0xffffffffu, pd, o);
        }
        if (tx == 0 && gr < N) { g_asrc[gr] = ps; g_adst[gr] = pd; }
    }
}

// ---------- K2: histogram of destinations (edges + self loops) ----------
__global__ __launch_bounds__(256)
void k_hist(const int* __restrict__ ei, int E, int N) {
    long long idx = (long long)blockIdx.x * blockDim.x + threadIdx.x;
    long long ET = (long long)E + N;
    if (idx >= ET) return;
    int d = (idx < E) ? clampi(ei[E + idx], N) : (int)(idx - E);
    atomicAdd(&g_count[d], 1);
}

// ---------- K3a/b/c: exclusive prefix sum of g_count -> g_rowstart, g_cursor ----------
__global__ __launch_bounds__(SCAN_B)
void k_scan_block(int N) {
    __shared__ int sm[SCAN_B];
    int tid = threadIdx.x;
    int i = blockIdx.x * SCAN_B + tid;
    int v = (i < N) ? g_count[i] : 0;
    sm[tid] = v; __syncthreads();
#pragma unroll
    for (int off = 1; off < SCAN_B; off <<= 1) {
        int t = (tid >= off) ? sm[tid - off] : 0;
        __syncthreads();
        sm[tid] += t;
        __syncthreads();
    }
    if (i < N) g_rowstart[i] = sm[tid] - v;        // exclusive within block
    if (tid == SCAN_B - 1) g_part[blockIdx.x] = sm[tid];
}

__global__ __launch_bounds__(1024)
void k_scan_top(int NP) {
    __shared__ int sm[1024];
    int tid = threadIdx.x;
    int v = (tid < NP) ? g_part[tid] : 0;
    sm[tid] = v; __syncthreads();
#pragma unroll
    for (int off = 1; off < 1024; off <<= 1) {
        int t = (tid >= off) ? sm[tid - off] : 0;
        __syncthreads();
        sm[tid] += t;
        __syncthreads();
    }
    if (tid < NP) g_part[tid] = sm[tid] - v;       // exclusive block offsets
}

__global__ __launch_bounds__(256)
void k_scan_add(int N) {
    int i = blockIdx.x * blockDim.x + threadIdx.x;
    if (i >= N) return;
    int r = g_rowstart[i] + g_part[i / SCAN_B];
    g_rowstart[i] = r;
    g_cursor[i] = r;
}

// ---------- K4: bucket edge sources by destination ----------
__global__ __launch_bounds__(256)
void k_bucket(const int* __restrict__ ei, int E, int N) {
    long long idx = (long long)blockIdx.x * blockDim.x + threadIdx.x;
    long long ET = (long long)E + N;
    if (idx >= ET) return;
    int s, d;
    if (idx < E) { s = clampi(ei[idx], N); d = clampi(ei[E + idx], N); }
    else         { s = d = (int)(idx - E); }
    int pos = atomicAdd(&g_cursor[d], 1);
    g_esrc[pos] = s;
}

// ---------- K5: warp-per-destination gather: softmax + aggregate + bias + L2norm ----------
__global__ __launch_bounds__(256)
void k_gather(const float* __restrict__ bias, float* __restrict__ out, int N) {
    int warp = (blockIdx.x * blockDim.x + threadIdx.x) >> 5;
    int lane = threadIdx.x & 31;
    if (warp >= N) return;
    const int d = warp;
    const int start = g_rowstart[d];
    const int deg = g_count[d];          // >= 1 (self loop)
    const float adst = g_adst[d];

    // pass 1: segment max (lanes stride edges)
    float m = -3.4028235e38f;
    for (int i = lane; i < deg; i += 32) {
        int s = g_esrc[start + i];
        m = fmaxf(m, lrelu(g_asrc[s] + adst));
    }
#pragma unroll
    for (int o = 16; o >= 1; o >>= 1) m = fmaxf(m, __shfl_xor_sync(0xffffffffu, m, o));

    // pass 2: weighted accumulate; each lane owns 2 output cols.
    // w identical in all lanes -> denom accumulated redundantly (no reduction).
    float ax = 0.f, ay = 0.f, dsum = 0.f;
    int i = 0;
#pragma unroll 1
    for (; i + 2 <= deg; i += 2) {
        int s0 = g_esrc[start + i];
        int s1 = g_esrc[start + i + 1];
        float w0 = __expf(lrelu(g_asrc[s0] + adst) - m);
        float w1 = __expf(lrelu(g_asrc[s1] + adst) - m);
        float2 h0 = *(const float2*)&g_h[(size_t)s0 * OUT_DIM + lane * 2];
        float2 h1 = *(const float2*)&g_h[(size_t)s1 * OUT_DIM + lane * 2];
        dsum += w0 + w1;
        ax += w0 * h0.x + w1 * h1.x;
        ay += w0 * h0.y + w1 * h1.y;
    }
    if (i < deg) {
        int s0 = g_esrc[start + i];
        float w0 = __expf(lrelu(g_asrc[s0] + adst) - m);
        float2 h0 = *(const float2*)&g_h[(size_t)s0 * OUT_DIM + lane * 2];
        dsum += w0;
        ax += w0 * h0.x;
        ay += w0 * h0.y;
    }

    float inv = 1.f / dsum;
    float2 bv = *(const float2*)&bias[lane * 2];
    float o0 = ax * inv + bv.x;
    float o1 = ay * inv + bv.y;
    float ss = o0 * o0 + o1 * o1;
#pragma unroll
    for (int o = 16; o >= 1; o >>= 1) ss += __shfl_xor_sync(0xffffffffu, ss, o);
    float sc = 1.f / fmaxf(sqrtf(ss), 1e-12f);
    *(float2*)&out[(size_t)d * OUT_DIM + lane * 2] = make_float2(o0 * sc, o1 * sc);
}

static inline int grid1(long long work, int block) {
    long long g = (work + block - 1) / block;
    return (int)(g < 1 ? 1 : g);
}

extern "C" void kernel_launch(void* const* d_in, const int* in_sizes, int n_in,
                              void* d_out, int out_size) {
    const float* x     = (const float*)d_in[0];
    const int*   ei    = (const int*)d_in[1];     // int32 (JAX x64 disabled)
    const float* W     = (const float*)d_in[2];
    const float* att_s = (const float*)d_in[3];
    const float* att_d = (const float*)d_in[4];
    const float* bias  = (const float*)d_in[5];
    float* out = (float*)d_out;

    int       N  = in_sizes[0] / IN_DIM;
    int       E  = in_sizes[1] / 2;
    long long ET = (long long)E + N;
    int       NP = (N + SCAN_B - 1) / SCAN_B;     // <= 1024 for N <= 524288

    k_init<<<grid1(N, 256), 256>>>(N);
    k_gemm<<<grid1(N, TM), 256>>>(x, W, att_s, att_d, N);
    k_hist<<<grid1(ET, 256), 256>>>(ei, E, N);
    k_scan_block<<<NP, SCAN_B>>>(N);
    k_scan_top<<<1, 1024>>>(NP);
    k_scan_add<<<grid1(N, 256), 256>>>(N);
    k_bucket<<<grid1(ET, 256), 256>>>(ei, E, N);
    k_gather<<<grid1((long long)N * 32, 256), 256>>>(bias, out, N);
}

// round 15
// speedup vs baseline: 1.3934x; 1.1186x over previous
#include <cuda_runtime.h>

typedef unsigned long long ull;

// Fixed problem shape: N=100000, IN=256, OUT=64, E=1600000 (guarded by in_sizes).
#define NMAX 100000
#define EMAX 1600000
#define ETMAX (NMAX + EMAX)
#define IN_DIM 256
#define OUT_DIM 64

__device__ __align__(16) float g_h[(size_t)NMAX * OUT_DIM];
__device__ float g_asrc[NMAX];
__device__ float g_adst[NMAX];
__device__ float g_amax;             // global max of asrc (upper bound)
__device__ int   g_total;            // bucket allocation cursor
__device__ int   g_count[NMAX];      // in-degree (incl self loop)
__device__ int   g_rowstart[NMAX];   // bucket base per dst (disjoint, unordered)
__device__ int   g_cursor[NMAX];     // bucket-fill cursor
__device__ int   g_esrc[ETMAX];      // edge sources bucketed by dst

// ---------- packed f32x2 helpers (Blackwell) ----------
__device__ __forceinline__ ull packdup(float v) {
    ull r; asm("mov.b64 %0, {%1, %1};" : "=l"(r) : "f"(v)); return r;
}
__device__ __forceinline__ void fma2(ull& d, ull a, ull b) {
    asm("fma.rn.f32x2 %0, %1, %2, %0;" : "+l"(d) : "l"(a), "l"(b));
}
__device__ __forceinline__ void unpack2(ull v, float& a, float& b) {
    asm("mov.b64 {%0, %1}, %2;" : "=f"(a), "=f"(b) : "l"(v));
}

__device__ __forceinline__ void atomicMaxF(float* addr, float val) {
    if (val >= 0.f) atomicMax((int*)addr, __float_as_int(val));
    else            atomicMin((unsigned int*)addr, __float_as_uint(val));
}

__device__ __forceinline__ float lrelu(float v) {
    return fmaxf(v, 0.f) + 0.2f * fminf(v, 0.f);
}
__device__ __forceinline__ int clampi(int v, int hi) { return min(max(v, 0), hi - 1); }

// ---------- K0: zero counters ----------
__global__ void k_init(int N) {
    int i = blockIdx.x * blockDim.x + threadIdx.x;
    if (i < N) g_count[i] = 0;
    if (i == 0) { g_total = 0; g_amax = __int_as_float(0xff800000); }
}

// ---------- K1: h = x @ W, a_src/a_dst scores, global asrc max ----------
// 128x64 tile, 256 threads, 8x4 register tile.
// xs stored transposed [k][m] with XOR swizzle at float4 granularity:
// conflict-free scalar transpose stores + aligned conflict-free LDS.128 loads.
#define TM 128
#define TK 32
__global__ __launch_bounds__(256)
void k_gemm(const float* __restrict__ x, const float* __restrict__ W,
            const float* __restrict__ att_s, const float* __restrict__ att_d, int N) {
    __shared__ float xs[TK][TM];       // [k][m], m-chunks XOR-swizzled by (k>>2)&7
    __shared__ float ws[TK][OUT_DIM];  // [k][n]

    const int tid = threadIdx.x;
    const int tx = tid & 15;          // 4 cols each
    const int ty = tid >> 4;          // 8 rows each (16 groups * 8 = 128)
    const int row0 = blockIdx.x * TM;

    ull acc[8][2];
#pragma unroll
    for (int i = 0; i < 8; i++) { acc[i][0] = 0ull; acc[i][1] = 0ull; }

    for (int kc = 0; kc < IN_DIM; kc += TK) {
        // x tile: 128 rows x 32 k = 1024 float4, transposed into xs[k][m]
#pragma unroll
        for (int it = 0; it < 4; ++it) {
            int idx = tid + it * 256;          // 0..1023
            int m   = idx >> 3;                // row in tile
            int kq  = idx & 7;                 // float4-of-k
            int gr  = row0 + m;
            float4 v = make_float4(0.f, 0.f, 0.f, 0.f);
            if (gr < N) v = *(const float4*)(x + (long long)gr * IN_DIM + kc + kq * 4);
            // scalar stores to 4 k-rows; swizzle m4 by kq
            int msw = ((m >> 2) ^ kq) * 4 + (m & 3);
            xs[kq * 4 + 0][msw] = v.x;
            xs[kq * 4 + 1][msw] = v.y;
            xs[kq * 4 + 2][msw] = v.z;
            xs[kq * 4 + 3][msw] = v.w;
        }
        // W tile: 32 k x 64 n = 512 float4
#pragma unroll
        for (int it = 0; it < 2; ++it) {
            int idx = tid + it * 256;
            int k   = idx >> 4;
            int nq  = idx & 15;
            *(float4*)&ws[k][nq * 4] =
                *(const float4*)(W + (long long)(kc + k) * OUT_DIM + nq * 4);
        }
        __syncthreads();

#pragma unroll
        for (int k = 0; k < TK; ++k) {
            int kq = k >> 2;
            float4 xa = *(const float4*)&xs[k][((ty * 2 + 0) ^ kq) * 4];
            float4 xb = *(const float4*)&xs[k][((ty * 2 + 1) ^ kq) * 4];
            ulonglong2 bv = *(const ulonglong2*)&ws[k][tx * 4];
            ull A;
            A = packdup(xa.x); fma2(acc[0][0], A, bv.x); fma2(acc[0][1], A, bv.y);
            A = packdup(xa.y); fma2(acc[1][0], A, bv.x); fma2(acc[1][1], A, bv.y);
            A = packdup(xa.z); fma2(acc[2][0], A, bv.x); fma2(acc[2][1], A, bv.y);
            A = packdup(xa.w); fma2(acc[3][0], A, bv.x); fma2(acc[3][1], A, bv.y);
            A = packdup(xb.x); fma2(acc[4][0], A, bv.x); fma2(acc[4][1], A, bv.y);
            A = packdup(xb.y); fma2(acc[5][0], A, bv.x); fma2(acc[5][1], A, bv.y);
            A = packdup(xb.z); fma2(acc[6][0], A, bv.x); fma2(acc[6][1], A, bv.y);
            A = packdup(xb.w); fma2(acc[7][0], A, bv.x); fma2(acc[7][1], A, bv.y);
        }
        __syncthreads();
    }

    float as[4], ad[4];
#pragma unroll
    for (int j = 0; j < 4; j++) { as[j] = att_s[tx * 4 + j]; ad[j] = att_d[tx * 4 + j]; }

    float pmax = -3.4028235e38f;
#pragma unroll
    for (int r = 0; r < 8; r++) {
        float f0, f1, f2, f3;
        unpack2(acc[r][0], f0, f1);
        unpack2(acc[r][1], f2, f3);
        int gr = row0 + ty * 8 + r;
        if (gr < N)
            *(float4*)&g_h[(long long)gr * OUT_DIM + tx * 4] =
                make_float4(f0, f1, f2, f3);
        float ps = f0 * as[0] + f1 * as[1] + f2 * as[2] + f3 * as[3];
        float pd = f0 * ad[0] + f1 * ad[1] + f2 * ad[2] + f3 * ad[3];
#pragma unroll
        for (int o = 8; o >= 1; o >>= 1) {
            ps += __shfl_xor_sync(0xffffffffu, ps, o);
            pd += __shfl_xor_sync(0xffffffffu, pd, o);
        }
        if (tx == 0 && gr < N) { g_asrc[gr] = ps; g_adst[gr] = pd; }
        pmax = fmaxf(pmax, ps);   // all lanes hold reduced ps; includes 0 for pad rows (still valid upper bound)
    }
    // one atomic per warp
#pragma unroll
    for (int o = 16; o >= 1; o >>= 1) pmax = fmaxf(pmax, __shfl_xor_sync(0xffffffffu, pmax, o));
    if ((tid & 31) == 0) atomicMaxF(&g_amax, pmax);
}

// ---------- K2: histogram of destinations (edges + self loops) ----------
__global__ __launch_bounds__(256)
void k_hist(const int* __restrict__ ei, int E, int N) {
    long long idx = (long long)blockIdx.x * blockDim.x + threadIdx.x;
    long long ET = (long long)E + N;
    if (idx >= ET) return;
    int d = (idx < E) ? clampi(ei[E + idx], N) : (int)(idx - E);
    atomicAdd(&g_count[d], 1);
}

// ---------- K3: allocate disjoint buckets (order-free; warp-aggregated atomic) ----------
__global__ __launch_bounds__(256)
void k_alloc(int N) {
    int i = blockIdx.x * blockDim.x + threadIdx.x;
    int lane = threadIdx.x & 31;
    int v = (i < N) ? g_count[i] : 0;
    int incl = v;
#pragma unroll
    for (int o = 1; o < 32; o <<= 1) {
        int t = __shfl_up_sync(0xffffffffu, incl, o);
        if (lane >= o) incl += t;
    }
    int total = __shfl_sync(0xffffffffu, incl, 31);
    int base = 0;
    if (lane == 31) base = atomicAdd(&g_total, total);
    base = __shfl_sync(0xffffffffu, base, 31);
    int start = base + incl - v;
    if (i < N) { g_rowstart[i] = start; g_cursor[i] = start; }
}

// ---------- K4: bucket edge sources by destination ----------
__global__ __launch_bounds__(256)
void k_bucket(const int* __restrict__ ei, int E, int N) {
    long long idx = (long long)blockIdx.x * blockDim.x + threadIdx.x;
    long long ET = (long long)E + N;
    if (idx >= ET) return;
    int s, d;
    if (idx < E) { s = clampi(ei[idx], N); d = clampi(ei[E + idx], N); }
    else         { s = d = (int)(idx - E); }
    int pos = atomicAdd(&g_cursor[d], 1);
    g_esrc[pos] = s;
}

// ---------- K5: warp-per-destination single-pass gather ----------
// Softmax shift uses m = lrelu(amax + adst) >= every segment value (lrelu monotone),
// mathematically identical alphas (softmax shift invariance), no overflow.
__global__ __launch_bounds__(256)
void k_gather(const float* __restrict__ bias, float* __restrict__ out, int N) {
    int warp = (blockIdx.x * blockDim.x + threadIdx.x) >> 5;
    int lane = threadIdx.x & 31;
    if (warp >= N) return;
    const int d = warp;
    const int start = g_rowstart[d];
    const int deg = g_count[d];          // >= 1 (self loop)
    const float adst = g_adst[d];
    const float m = lrelu(g_amax + adst);

    float ax = 0.f, ay = 0.f, dsum = 0.f;
    int i = 0;
#pragma unroll 1
    for (; i + 4 <= deg; i += 4) {
        int s0 = g_esrc[start + i + 0];
        int s1 = g_esrc[start + i + 1];
        int s2 = g_esrc[start + i + 2];
        int s3 = g_esrc[start + i + 3];
        float w0 = __expf(lrelu(g_asrc[s0] + adst) - m);
        float w1 = __expf(lrelu(g_asrc[s1] + adst) - m);
        float w2 = __expf(lrelu(g_asrc[s2] + adst) - m);
        float w3 = __expf(lrelu(g_asrc[s3] + adst) - m);
        float2 h0 = *(const float2*)&g_h[(size_t)s0 * OUT_DIM + lane * 2];
        float2 h1 = *(const float2*)&g_h[(size_t)s1 * OUT_DIM + lane * 2];
        float2 h2 = *(const float2*)&g_h[(size_t)s2 * OUT_DIM + lane * 2];
        float2 h3 = *(const float2*)&g_h[(size_t)s3 * OUT_DIM + lane * 2];
        dsum += (w0 + w1) + (w2 + w3);
        ax += w0 * h0.x + w1 * h1.x + w2 * h2.x + w3 * h3.x;
        ay += w0 * h0.y + w1 * h1.y + w2 * h2.y + w3 * h3.y;
    }
#pragma unroll 1
    for (; i < deg; ++i) {
        int s0 = g_esrc[start + i];
        float w0 = __expf(lrelu(g_asrc[s0] + adst) - m);
        float2 h0 = *(const float2*)&g_h[(size_t)s0 * OUT_DIM + lane * 2];
        dsum += w0;
        ax += w0 * h0.x;
        ay += w0 * h0.y;
    }

    float inv = 1.f / dsum;
    float2 bv = *(const float2*)&bias[lane * 2];
    float o0 = ax * inv + bv.x;
    float o1 = ay * inv + bv.y;
    float ss = o0 * o0 + o1 * o1;
#pragma unroll
    for (int o = 16; o >= 1; o >>= 1) ss += __shfl_xor_sync(0xffffffffu, ss, o);
    float sc = 1.f / fmaxf(sqrtf(ss), 1e-12f);
    *(float2*)&out[(size_t)d * OUT_DIM + lane * 2] = make_float2(o0 * sc, o1 * sc);
}

static inline int grid1(long long work, int block) {
    long long g = (work + block - 1) / block;
    return (int)(g < 1 ? 1 : g);
}

extern "C" void kernel_launch(void* const* d_in, const int* in_sizes, int n_in,
                              void* d_out, int out_size) {
    const float* x     = (const float*)d_in[0];
    const int*   ei    = (const int*)d_in[1];     // int32 (JAX x64 disabled)
    const float* W     = (const float*)d_in[2];
    const float* att_s = (const float*)d_in[3];
    const float* att_d = (const float*)d_in[4];
    const float* bias  = (const float*)d_in[5];
    float* out = (float*)d_out;

    int       N  = in_sizes[0] / IN_DIM;
    int       E  = in_sizes[1] / 2;
    long long ET = (long long)E + N;

    k_init<<<grid1(N, 256), 256>>>(N);
    k_gemm<<<grid1(N, TM), 256>>>(x, W, att_s, att_d, N);
    k_hist<<<grid1(ET, 256), 256>>>(ei, E, N);
    k_alloc<<<grid1(N, 256), 256>>>(N);
    k_bucket<<<grid1(ET, 256), 256>>>(ei, E, N);
    k_gather<<<grid1((long long)N * 32, 256), 256>>>(bias, out, N);
}

// round 16
// speedup vs baseline: 1.5001x; 1.0766x over previous
#include <cuda_runtime.h>

typedef unsigned long long ull;

// Fixed problem shape: N=100000, IN=256, OUT=64, E=1600000 (guarded by in_sizes).
#define NMAX 100000
#define EMAX 1600000
#define ETMAX (NMAX + EMAX)
#define IN_DIM 256
#define OUT_DIM 64

__device__ __align__(16) float g_h[(size_t)NMAX * OUT_DIM];
__device__ float g_asrc[NMAX];
__device__ float g_adst[NMAX];
__device__ float g_amax;             // global max of asrc (upper bound)
__device__ int   g_total;            // bucket allocation cursor
__device__ int   g_count[NMAX];      // in-degree (incl self loop)
__device__ int   g_rowstart[NMAX];   // bucket base per dst (disjoint, unordered)
__device__ int   g_cursor[NMAX];     // bucket-fill cursor
__device__ __align__(8) int2 g_edge[ETMAX];  // (src, exp-weight bits) bucketed by dst

// ---------- packed f32x2 helpers (Blackwell) ----------
__device__ __forceinline__ ull packdup(float v) {
    ull r; asm("mov.b64 %0, {%1, %1};" : "=l"(r) : "f"(v)); return r;
}
__device__ __forceinline__ void fma2(ull& d, ull a, ull b) {
    asm("fma.rn.f32x2 %0, %1, %2, %0;" : "+l"(d) : "l"(a), "l"(b));
}
__device__ __forceinline__ void unpack2(ull v, float& a, float& b) {
    asm("mov.b64 {%0, %1}, %2;" : "=f"(a), "=f"(b) : "l"(v));
}

__device__ __forceinline__ void atomicMaxF(float* addr, float val) {
    if (val >= 0.f) atomicMax((int*)addr, __float_as_int(val));
    else            atomicMin((unsigned int*)addr, __float_as_uint(val));
}

__device__ __forceinline__ float lrelu(float v) {
    return fmaxf(v, 0.f) + 0.2f * fminf(v, 0.f);
}
__device__ __forceinline__ int clampi(int v, int hi) { return min(max(v, 0), hi - 1); }

// ---------- K0: zero counters ----------
__global__ void k_init(int N) {
    int i = blockIdx.x * blockDim.x + threadIdx.x;
    if (i < N) g_count[i] = 0;
    if (i == 0) { g_total = 0; g_amax = __int_as_float(0xff800000); }
}

// ---------- K1: h = x @ W, a_src/a_dst scores, global asrc max ----------
#define TM 128
#define TK 32
__global__ __launch_bounds__(256)
void k_gemm(const float* __restrict__ x, const float* __restrict__ W,
            const float* __restrict__ att_s, const float* __restrict__ att_d, int N) {
    __shared__ float xs[TK][TM];       // [k][m], m-chunks XOR-swizzled by (k>>2)&7
    __shared__ float ws[TK][OUT_DIM];  // [k][n]

    const int tid = threadIdx.x;
    const int tx = tid & 15;
    const int ty = tid >> 4;
    const int row0 = blockIdx.x * TM;

    ull acc[8][2];
#pragma unroll
    for (int i = 0; i < 8; i++) { acc[i][0] = 0ull; acc[i][1] = 0ull; }

    for (int kc = 0; kc < IN_DIM; kc += TK) {
#pragma unroll
        for (int it = 0; it < 4; ++it) {
            int idx = tid + it * 256;
            int m   = idx >> 3;
            int kq  = idx & 7;
            int gr  = row0 + m;
            float4 v = make_float4(0.f, 0.f, 0.f, 0.f);
            if (gr < N) v = *(const float4*)(x + (long long)gr * IN_DIM + kc + kq * 4);
            int msw = ((m >> 2) ^ kq) * 4 + (m & 3);
            xs[kq * 4 + 0][msw] = v.x;
            xs[kq * 4 + 1][msw] = v.y;
            xs[kq * 4 + 2][msw] = v.z;
            xs[kq * 4 + 3][msw] = v.w;
        }
#pragma unroll
        for (int it = 0; it < 2; ++it) {
            int idx = tid + it * 256;
            int k   = idx >> 4;
            int nq  = idx & 15;
            *(float4*)&ws[k][nq * 4] =
                *(const float4*)(W + (long long)(kc + k) * OUT_DIM + nq * 4);
        }
        __syncthreads();

#pragma unroll
        for (int k = 0; k < TK; ++k) {
            int kq = k >> 2;
            float4 xa = *(const float4*)&xs[k][((ty * 2 + 0) ^ kq) * 4];
            float4 xb = *(const float4*)&xs[k][((ty * 2 + 1) ^ kq) * 4];
            ulonglong2 bv = *(const ulonglong2*)&ws[k][tx * 4];
            ull A;
            A = packdup(xa.x); fma2(acc[0][0], A, bv.x); fma2(acc[0][1], A, bv.y);
            A = packdup(xa.y); fma2(acc[1][0], A, bv.x); fma2(acc[1][1], A, bv.y);
            A = packdup(xa.z); fma2(acc[2][0], A, bv.x); fma2(acc[2][1], A, bv.y);
            A = packdup(xa.w); fma2(acc[3][0], A, bv.x); fma2(acc[3][1], A, bv.y);
            A = packdup(xb.x); fma2(acc[4][0], A, bv.x); fma2(acc[4][1], A, bv.y);
            A = packdup(xb.y); fma2(acc[5][0], A, bv.x); fma2(acc[5][1], A, bv.y);
            A = packdup(xb.z); fma2(acc[6][0], A, bv.x); fma2(acc[6][1], A, bv.y);
            A = packdup(xb.w); fma2(acc[7][0], A, bv.x); fma2(acc[7][1], A, bv.y);
        }
        __syncthreads();
    }

    float as[4], ad[4];
#pragma unroll
    for (int j = 0; j < 4; j++) { as[j] = att_s[tx * 4 + j]; ad[j] = att_d[tx * 4 + j]; }

    float pmax = -3.4028235e38f;
#pragma unroll
    for (int r = 0; r < 8; r++) {
        float f0, f1, f2, f3;
        unpack2(acc[r][0], f0, f1);
        unpack2(acc[r][1], f2, f3);
        int gr = row0 + ty * 8 + r;
        if (gr < N)
            *(float4*)&g_h[(long long)gr * OUT_DIM + tx * 4] =
                make_float4(f0, f1, f2, f3);
        float ps = f0 * as[0] + f1 * as[1] + f2 * as[2] + f3 * as[3];
        float pd = f0 * ad[0] + f1 * ad[1] + f2 * ad[2] + f3 * ad[3];
#pragma unroll
        for (int o = 8; o >= 1; o >>= 1) {
            ps += __shfl_xor_sync(0xffffffffu, ps, o);
            pd += __shfl_xor_sync(0xffffffffu, pd, o);
        }
        if (tx == 0 && gr < N) { g_asrc[gr] = ps; g_adst[gr] = pd; }
        pmax = fmaxf(pmax, ps);
    }
#pragma unroll
    for (int o = 16; o >= 1; o >>= 1) pmax = fmaxf(pmax, __shfl_xor_sync(0xffffffffu, pmax, o));
    if ((tid & 31) == 0) atomicMaxF(&g_amax, pmax);
}

// ---------- K2: histogram of destinations (edges + self loops) ----------
__global__ __launch_bounds__(256)
void k_hist(const int* __restrict__ ei, int E, int N) {
    long long idx = (long long)blockIdx.x * blockDim.x + threadIdx.x;
    long long ET = (long long)E + N;
    if (idx >= ET) return;
    int d = (idx < E) ? clampi(ei[E + idx], N) : (int)(idx - E);
    atomicAdd(&g_count[d], 1);
}

// ---------- K3: allocate disjoint buckets; 4 nodes/thread, warp-aggregated atomic ----------
__global__ __launch_bounds__(256)
void k_alloc(int N) {
    int t = blockIdx.x * blockDim.x + threadIdx.x;
    int lane = threadIdx.x & 31;
    int i0 = t * 4;
    int c[4];
#pragma unroll
    for (int j = 0; j < 4; j++) c[j] = (i0 + j < N) ? g_count[i0 + j] : 0;
    int local = c[0] + c[1] + c[2] + c[3];
    int incl = local;
#pragma unroll
    for (int o = 1; o < 32; o <<= 1) {
        int v = __shfl_up_sync(0xffffffffu, incl, o);
        if (lane >= o) incl += v;
    }
    int total = __shfl_sync(0xffffffffu, incl, 31);
    int base = 0;
    if (lane == 31) base = atomicAdd(&g_total, total);
    base = __shfl_sync(0xffffffffu, base, 31);
    int start = base + incl - local;
#pragma unroll
    for (int j = 0; j < 4; j++) {
        if (i0 + j < N) { g_rowstart[i0 + j] = start; g_cursor[i0 + j] = start; }
        start += c[j];
    }
}

// ---------- K4: bucket edges by destination; precompute softmax weight once/edge ----------
// Softmax shift m = lrelu(amax + adst) >= every segment value (lrelu monotone);
// alphas identical by shift invariance; gap <= asrc spread -> no underflow risk.
__global__ __launch_bounds__(256)
void k_bucket(const int* __restrict__ ei, int E, int N) {
    long long idx = (long long)blockIdx.x * blockDim.x + threadIdx.x;
    long long ET = (long long)E + N;
    if (idx >= ET) return;
    int s, d;
    if (idx < E) { s = clampi(ei[idx], N); d = clampi(ei[E + idx], N); }
    else         { s = d = (int)(idx - E); }
    float adst = g_adst[d];
    float w = __expf(lrelu(g_asrc[s] + adst) - lrelu(g_amax + adst));
    int pos = atomicAdd(&g_cursor[d], 1);
    g_edge[pos] = make_int2(s, __float_as_int(w));
}

// ---------- K5: warp-per-destination gather: pure weighted aggregation ----------
__global__ __launch_bounds__(256)
void k_gather(const float* __restrict__ bias, float* __restrict__ out, int N) {
    int warp = (blockIdx.x * blockDim.x + threadIdx.x) >> 5;
    int lane = threadIdx.x & 31;
    if (warp >= N) return;
    const int d = warp;
    const int start = g_rowstart[d];
    const int deg = g_count[d];          // >= 1 (self loop)

    float ax = 0.f, ay = 0.f, dsum = 0.f;
    int i = 0;
#pragma unroll 1
    for (; i + 4 <= deg; i += 4) {
        int2 e0 = g_edge[start + i + 0];
        int2 e1 = g_edge[start + i + 1];
        int2 e2 = g_edge[start + i + 2];
        int2 e3 = g_edge[start + i + 3];
        float w0 = __int_as_float(e0.y);
        float w1 = __int_as_float(e1.y);
        float w2 = __int_as_float(e2.y);
        float w3 = __int_as_float(e3.y);
        float2 h0 = *(const float2*)&g_h[(size_t)e0.x * OUT_DIM + lane * 2];
        float2 h1 = *(const float2*)&g_h[(size_t)e1.x * OUT_DIM + lane * 2];
        float2 h2 = *(const float2*)&g_h[(size_t)e2.x * OUT_DIM + lane * 2];
        float2 h3 = *(const float2*)&g_h[(size_t)e3.x * OUT_DIM + lane * 2];
        dsum += (w0 + w1) + (w2 + w3);
        ax += w0 * h0.x + w1 * h1.x + w2 * h2.x + w3 * h3.x;
        ay += w0 * h0.y + w1 * h1.y + w2 * h2.y + w3 * h3.y;
    }
#pragma unroll 1
    for (; i < deg; ++i) {
        int2 e0 = g_edge[start + i];
        float w0 = __int_as_float(e0.y);
        float2 h0 = *(const float2*)&g_h[(size_t)e0.x * OUT_DIM + lane * 2];
        dsum += w0;
        ax += w0 * h0.x;
        ay += w0 * h0.y;
    }

    float inv = 1.f / dsum;
    float2 bv = *(const float2*)&bias[lane * 2];
    float o0 = ax * inv + bv.x;
    float o1 = ay * inv + bv.y;
    float ss = o0 * o0 + o1 * o1;
#pragma unroll
    for (int o = 16; o >= 1; o >>= 1) ss += __shfl_xor_sync(0xffffffffu, ss, o);
    float sc = 1.f / fmaxf(sqrtf(ss), 1e-12f);
    *(float2*)&out[(size_t)d * OUT_DIM + lane * 2] = make_float2(o0 * sc, o1 * sc);
}

static inline int grid1(long long work, int block) {
    long long g = (work + block - 1) / block;
    return (int)(g < 1 ? 1 : g);
}

extern "C" void kernel_launch(void* const* d_in, const int* in_sizes, int n_in,
                              void* d_out, int out_size) {
    const float* x     = (const float*)d_in[0];
    const int*   ei    = (const int*)d_in[1];     // int32 (JAX x64 disabled)
    const float* W     = (const float*)d_in[2];
    const float* att_s = (const float*)d_in[3];
    const float* att_d = (const float*)d_in[4];
    const float* bias  = (const float*)d_in[5];
    float* out = (float*)d_out;

    int       N  = in_sizes[0] / IN_DIM;
    int       E  = in_sizes[1] / 2;
    long long ET = (long long)E + N;

    k_init<<<grid1(N, 256), 256>>>(N);
    k_gemm<<<grid1(N, TM), 256>>>(x, W, att_s, att_d, N);
    k_hist<<<grid1(ET, 256), 256>>>(ei, E, N);
    k_alloc<<<grid1((N + 3) / 4, 256), 256>>>(N);
    k_bucket<<<grid1(ET, 256), 256>>>(ei, E, N);
    k_gather<<<grid1((long long)N * 32, 256), 256>>>(bias, out, N);
}